// round 14
// baseline (speedup 1.0000x reference)
#include <cuda_runtime.h>
#include <math.h>

#define B_ 512
#define T_ 512

// Scratch (static __device__ arrays: allocation-free per harness rules)
__device__ float g_xw0[(size_t)T_ * B_ * 16];   // layer0 input projection [t][b][16]
__device__ float g_hlast[B_ * 70];
__device__ float g_dummy[32];

// ---------------------------------------------------------------------------
// helpers
// ---------------------------------------------------------------------------
__device__ __forceinline__ void ffma2_acc(float2& acc, float2 a, float2 b) {
    asm("fma.rn.f32x2 %0, %1, %2, %0;"
        : "+l"(reinterpret_cast<unsigned long long&>(acc))
        : "l"(reinterpret_cast<const unsigned long long&>(a)),
          "l"(reinterpret_cast<const unsigned long long&>(b)));
}
__device__ __forceinline__ float2 sh2(float2 v, int m) {
    float2 r;
    r.x = __shfl_xor_sync(0xffffffffu, v.x, m);
    r.y = __shfl_xor_sync(0xffffffffu, v.y, m);
    return r;
}
__device__ __forceinline__ float2 add2(float2 a, float2 b) {
    return make_float2(a.x + b.x, a.y + b.y);
}
// tanh(x) = sign(x)*(1 - e^{-2|x|})/(1 + e^{-2|x|}); denom in [1,2]. ~1e-7 abs err.
__device__ __forceinline__ float ftanh(float x) {
    float ax = fabsf(x);
    float t = __expf(-2.f * ax);
    float r = __fdividef(1.f - t, 1.f + t);
    return copysignf(r, x);
}
__global__ void dummy_kernel(float* p) { if (threadIdx.x == 0) p[0] = 1.f; }

// ---------------------------------------------------------------------------
// GEMM for layer-0 input projection (round-4 version, measured 62us)
// ---------------------------------------------------------------------------
template <int K, int N, int TM>
__global__ void __launch_bounds__((N / 4) * (TM / 4))
gemm0_kernel(const float* __restrict__ in, const float* __restrict__ W,
             const float* __restrict__ bias, float* __restrict__ out) {
    constexpr int NG4 = N / 4;
    constexpr int TMP = TM + 4;

    __shared__ __align__(16) float AshT[K * TMP];
    __shared__ __align__(16) float Wsh[K * N];

    const int tid  = threadIdx.x;
    const int nthr = blockDim.x;
    const int rM   = blockIdx.x * TM;

#pragma unroll 4
    for (int idx = tid; idx < K * N; idx += nthr) Wsh[idx] = W[idx];
#pragma unroll 8
    for (int idx = tid; idx < TM * K; idx += nthr) {
        int rr = idx / K, kk = idx % K;
        int r = rM + rr;
        int t = r >> 9;
        int b = r & (B_ - 1);
        AshT[kk * TMP + rr] = in[((size_t)b * T_ + t) * K + kk];
    }
    __syncthreads();

    const int tx  = tid % NG4;
    const int rid = tid / NG4;
    const int colb = 4 * tx;

    float4 bv = *(const float4*)&bias[colb];
    float4 acc0 = bv, acc1 = bv, acc2 = bv, acc3 = bv;

    const float4* Wp = (const float4*)Wsh;
#pragma unroll 4
    for (int k = 0; k < K; k++) {
        float4 a = *(const float4*)&AshT[k * TMP + rid * 4];
        float4 w = Wp[k * NG4 + tx];
        acc0.x = fmaf(a.x, w.x, acc0.x); acc0.y = fmaf(a.x, w.y, acc0.y);
        acc0.z = fmaf(a.x, w.z, acc0.z); acc0.w = fmaf(a.x, w.w, acc0.w);
        acc1.x = fmaf(a.y, w.x, acc1.x); acc1.y = fmaf(a.y, w.y, acc1.y);
        acc1.z = fmaf(a.y, w.z, acc1.z); acc1.w = fmaf(a.y, w.w, acc1.w);
        acc2.x = fmaf(a.z, w.x, acc2.x); acc2.y = fmaf(a.z, w.y, acc2.y);
        acc2.z = fmaf(a.z, w.z, acc2.z); acc2.w = fmaf(a.z, w.w, acc2.w);
        acc3.x = fmaf(a.w, w.x, acc3.x); acc3.y = fmaf(a.w, w.y, acc3.y);
        acc3.z = fmaf(a.w, w.z, acc3.z); acc3.w = fmaf(a.w, w.w, acc3.w);
    }
    float4 accs[4] = {acc0, acc1, acc2, acc3};
#pragma unroll
    for (int r = 0; r < 4; r++)
        *(float4*)&out[(size_t)(rM + rid * 4 + r) * N + colb] = accs[r];
}

// ---------------------------------------------------------------------------
// Fused wavefront RNN v7: v6 layout (batch-packed h, J=4 units/thread,
// 2B LDS per FFMA2) with 16 warps (4/SMSP) for latency overlap.
//   L3 H=70 D=134: 9 warps, P=16, C=9  (stride 9 f4, +1 f4 swizzle at row 72)
//   L2 H=64 D=96 : 4 warps, P=8,  C=12 (stride 13 f4)
//   L1 H=32 D=48 : 2 warps, P=8,  C=6  (stride 7 f4)
//   L0 H=16 D=16 : 1 warp,  P=8,  C=2  (stride 3 f4)
// Reduce-scatter butterfly (P=16 prepends an xor-8 allreduce; lanes p>=8
// compute duplicates and don't emit). Final lane owns (unit, batch-pair).
// ---------------------------------------------------------------------------
#define NBATCH   4
#define NTHREADS 512

#define VOFF0 0     /* size 24  */
#define VOFF1 24    /* size 56  */
#define VOFF2 80    /* size 104 */
#define VOFF3 184   /* size 146 */
#define VTOT  330

// weights for rows i = p*C + r, units j = jm*4 + jj, duplicated {u,u}
template <int C>
__device__ __forceinline__ void load_wv6(const float* __restrict__ U,
                                         const float* __restrict__ W,
                                         int HL, int INL, int jm, int p,
                                         float2 (&wreg)[48]) {
#pragma unroll
    for (int r = 0; r < C; r++) {
        int i = p * C + r;
#pragma unroll
        for (int jj = 0; jj < 4; jj++) {
            int j = jm * 4 + jj;
            float v = 0.f;
            if (j < HL && i < HL + INL)
                v = (i < HL) ? U[i * HL + j] : W[(i - HL) * HL + j];
            wreg[r * 4 + jj] = make_float2(v, v);
        }
    }
}

// accumulate + reduce-scatter + emit. P in {8,16}. Owner: q=p&7,
// unit = jm*4 + ((q>>1)&3), bp = q&1. For P=16 only lanes p<8 emit (valid).
template <int C, int P, bool L0F, bool LAST>
__device__ __forceinline__ void tick_v6(
    float* __restrict__ vinF, int prev, int cur,
    int loadBaseF4, const float2 (&wreg)[48],
    int p, bool valid, float2 bias2, float2 xr,
    int ownF, int mirF, int t, float* __restrict__ hlast,
    int hl0, int hl1)
{
    float2 a[8];
#pragma unroll
    for (int k = 0; k < 8; k++) a[k] = make_float2(0.f, 0.f);

    const float4* src = (const float4*)(vinF + (size_t)prev * (VTOT * 4)) + loadBaseF4;
#pragma unroll
    for (int r = 0; r < C; r++) {
        float4 hh = src[r];
        float2 h01 = make_float2(hh.x, hh.y);
        float2 h23 = make_float2(hh.z, hh.w);
#pragma unroll
        for (int jj = 0; jj < 4; jj++) {
            ffma2_acc(a[2 * jj],     h01, wreg[r * 4 + jj]);
            ffma2_acc(a[2 * jj + 1], h23, wreg[r * 4 + jj]);
        }
    }

    if constexpr (P == 16) {
        // combine the two C-halves (lanes p and p^8), keep all 8 items
#pragma unroll
        for (int k = 0; k < 8; k++) a[k] = add2(a[k], sh2(a[k], 8));
    }

    float* dst = vinF + (size_t)cur * (VTOT * 4);

    // scatter rounds over 8 lanes (q = p&7)
    bool s = (p & 4) != 0;
    float2 b[4];
#pragma unroll
    for (int k = 0; k < 4; k++) {
        float2 keep = s ? a[k + 4] : a[k];
        float2 send = s ? a[k] : a[k + 4];
        b[k] = add2(keep, sh2(send, 4));
    }
    s = (p & 2) != 0;
    float2 c[2];
#pragma unroll
    for (int k = 0; k < 2; k++) {
        float2 keep = s ? b[k + 2] : b[k];
        float2 send = s ? b[k] : b[k + 2];
        c[k] = add2(keep, sh2(send, 2));
    }
    s = (p & 1) != 0;
    {
        float2 keep = s ? c[1] : c[0];
        float2 send = s ? c[0] : c[1];
        float2 z = add2(keep, sh2(send, 1));
        if (valid) {
            if (L0F) z = add2(z, xr);
            else     z = add2(z, bias2);
            float t0 = ftanh(z.x);
            float t1 = ftanh(z.y);
            *(float2*)(dst + ownF) = make_float2(t0, t1);
            if (!LAST) {
                *(float2*)(dst + mirF) = make_float2(t0, t1);
            } else if (t == T_ - 1) {
                hlast[hl0] = t0;
                hlast[hl1] = t1;
            }
        }
    }
}

__global__ void __launch_bounds__(NTHREADS, 1)
fused_rnn_kernel(const float* __restrict__ xw0,
                 const float* __restrict__ U0,
                 const float* __restrict__ W1, const float* __restrict__ U1, const float* __restrict__ b1v,
                 const float* __restrict__ W2, const float* __restrict__ U2, const float* __restrict__ b2v,
                 const float* __restrict__ W3, const float* __restrict__ U3, const float* __restrict__ b3v,
                 float* __restrict__ hlast)
{
    __shared__ __align__(16) float4 vin[2][VTOT];
    float* vinF = (float*)vin;

    const int tid  = threadIdx.x;
    const int lane = tid & 31;
    const int wid  = tid >> 5;
    const int bbase = blockIdx.x * NBATCH;

    // SMSP-balanced warp->layer map (wid&3 = SMSP):
    // S0: w0(L3) w4(L3) w8(L2)  w12(L0)
    // S1: w1(L3) w5(L3) w9(L2)  w13(L1)
    // S2: w2(L3) w6(L3) w10(L2) w14(L1)
    // S3: w3(L3) w7(L3) w11(L3) w15(L2)
    int layer, lwarp;
    if (wid <= 7)        { layer = 3; lwarp = wid; }
    else if (wid == 11)  { layer = 3; lwarp = 8; }
    else if (wid <= 10)  { layer = 2; lwarp = wid - 8; }
    else if (wid == 15)  { layer = 2; lwarp = 3; }
    else if (wid >= 13)  { layer = 1; lwarp = wid - 13; }
    else                 { layer = 0; lwarp = 0; }  // wid == 12

    // per-thread decode
    int jm, p, unit = 0;
    bool valid = false;
    int loadBaseF4 = 0, ownF = 0, mirF = 0, hl0 = 0, hl1 = 0;
    float2 bias2 = make_float2(0.f, 0.f);
    float2 wreg[48];
#pragma unroll
    for (int k = 0; k < 48; k++) wreg[k] = make_float2(0.f, 0.f);

    int slot = lwarp * 32 + lane;

    if (layer == 3) {
        jm = slot >> 4; p = slot & 15;         // 18 groups, P=16
        int q = p & 7;
        int jj = (q >> 1) & 3, bp = q & 1;
        unit = jm * 4 + jj;
        valid = (unit < 70) && (p < 8);
        load_wv6<9>(U3, W3, 70, 64, jm, p, wreg);
        loadBaseF4 = VOFF3 + p * 9 + (p >> 3); // +1 f4 swizzle for upper half
        ownF = (VOFF3 + unit) * 4 + 2 * bp;    // own rows 0..69 (< 72: no shift)
        hl0 = (bbase + 2 * bp) * 70 + unit;
        hl1 = (bbase + 2 * bp + 1) * 70 + unit;
        if (unit < 70) { float bb = b3v[unit]; bias2 = make_float2(bb, bb); }
    } else if (layer == 2) {
        jm = slot >> 3; p = slot & 7;          // 16 groups, P=8
        int jj = (p >> 1) & 3, bp = p & 1;
        unit = jm * 4 + jj;
        valid = true;
        load_wv6<12>(U2, W2, 64, 32, jm, p, wreg);
        loadBaseF4 = VOFF2 + p * 13;
        ownF = (VOFF2 + unit + unit / 12) * 4 + 2 * bp;
        { int lu = 70 + unit; mirF = (VOFF3 + lu + (lu >= 72 ? 1 : 0)) * 4 + 2 * bp; }
        float bb = b2v[unit]; bias2 = make_float2(bb, bb);
    } else if (layer == 1) {
        jm = slot >> 3; p = slot & 7;          // 8 groups, P=8
        int jj = (p >> 1) & 3, bp = p & 1;
        unit = jm * 4 + jj;
        valid = true;
        load_wv6<6>(U1, W1, 32, 16, jm, p, wreg);
        loadBaseF4 = VOFF1 + p * 7;
        ownF = (VOFF1 + unit + unit / 6) * 4 + 2 * bp;
        { int lu = 64 + unit; mirF = (VOFF2 + lu + lu / 12) * 4 + 2 * bp; }
        float bb = b1v[unit]; bias2 = make_float2(bb, bb);
    } else {
        jm = lane >> 3; p = lane & 7;          // 4 groups, P=8
        int jj = (p >> 1) & 3, bp = p & 1;
        unit = jm * 4 + jj;
        valid = true;
        load_wv6<2>(U0, U0, 16, 0, jm, p, wreg);   // W unused (IN=0)
        loadBaseF4 = VOFF0 + p * 3;
        ownF = (VOFF0 + unit + unit / 2) * 4 + 2 * bp;
        { int lu = 32 + unit; mirF = (VOFF1 + lu + lu / 6) * 4 + 2 * bp; }
        hl0 = (bbase + 2 * bp) * 16 + unit;    // xw0 gather offsets
        hl1 = (bbase + 2 * bp + 1) * 16 + unit;
    }

    // zero both vin buffers (incl. pads)
    for (int i = tid; i < 2 * VTOT; i += NTHREADS)
        ((float4*)vin)[i] = make_float4(0.f, 0.f, 0.f, 0.f);

    // L0 xw ring, depth 3
    float2 xr0 = make_float2(0.f, 0.f), xr1 = xr0, xr2 = xr0;
    if (layer == 0) {
        xr0 = make_float2(xw0[(size_t)0 * 8192 + hl0], xw0[(size_t)0 * 8192 + hl1]);
        xr1 = make_float2(xw0[(size_t)1 * 8192 + hl0], xw0[(size_t)1 * 8192 + hl1]);
        xr2 = make_float2(xw0[(size_t)2 * 8192 + hl0], xw0[(size_t)2 * 8192 + hl1]);
    }
    __syncthreads();

    for (int tau = 0; tau < T_ + 3; tau++) {
        const int prev = (tau + 1) & 1;
        const int cur  = tau & 1;

        if (layer == 3) {
            int t = tau - 3;
            if (t >= 0 && t < T_)
                tick_v6<9, 16, false, true>(vinF, prev, cur, loadBaseF4, wreg,
                    p, valid, bias2, xr0, ownF, mirF, t, hlast, hl0, hl1);
        } else if (layer == 2) {
            int t = tau - 2;
            if (t >= 0 && t < T_)
                tick_v6<12, 8, false, false>(vinF, prev, cur, loadBaseF4, wreg,
                    p, valid, bias2, xr0, ownF, mirF, t, hlast, 0, 0);
        } else if (layer == 1) {
            int t = tau - 1;
            if (t >= 0 && t < T_)
                tick_v6<6, 8, false, false>(vinF, prev, cur, loadBaseF4, wreg,
                    p, valid, bias2, xr0, ownF, mirF, t, hlast, 0, 0);
        } else {
            if (tau < T_)
                tick_v6<2, 8, true, false>(vinF, prev, cur, loadBaseF4, wreg,
                    p, valid, bias2, xr0, ownF, mirF, tau, hlast, 0, 0);
            // rotate ring + prefetch t = tau+3
            int t3 = tau + 3;
            xr0 = xr1; xr1 = xr2;
            if (t3 < T_) {
                xr2 = make_float2(xw0[(size_t)t3 * 8192 + hl0],
                                  xw0[(size_t)t3 * 8192 + hl1]);
            }
        }

        __syncthreads();
    }
}

// ---------------------------------------------------------------------------
// Dense (70 -> 5) + softmax, smem-staged. grid 4 x block 128.
// ---------------------------------------------------------------------------
__global__ void __launch_bounds__(128)
dense_softmax_kernel(const float* __restrict__ h,
                     const float* __restrict__ Wd,
                     const float* __restrict__ bd,
                     float* __restrict__ out) {
    __shared__ float hs[128 * 70];
    __shared__ float Wds[70 * 5 + 5];

    const int tid = threadIdx.x;
    const int b0  = blockIdx.x * 128;

    for (int idx = tid; idx < 128 * 70; idx += 128)
        hs[idx] = h[(size_t)b0 * 70 + idx];
    for (int idx = tid; idx < 355; idx += 128)
        Wds[idx] = (idx < 350) ? Wd[idx] : bd[idx - 350];
    __syncthreads();

    float l[5];
#pragma unroll
    for (int c = 0; c < 5; c++) l[c] = Wds[350 + c];
#pragma unroll 2
    for (int k = 0; k < 70; k++) {
        float hv = hs[tid * 70 + k];
#pragma unroll
        for (int c = 0; c < 5; c++) l[c] = fmaf(hv, Wds[k * 5 + c], l[c]);
    }
    float m = l[0];
#pragma unroll
    for (int c = 1; c < 5; c++) m = fmaxf(m, l[c]);
    float s = 0.f;
#pragma unroll
    for (int c = 0; c < 5; c++) { l[c] = expf(l[c] - m); s += l[c]; }
    float inv = 1.f / s;
#pragma unroll
    for (int c = 0; c < 5; c++) out[(size_t)(b0 + tid) * 5 + c] = l[c] * inv;
}

// ---------------------------------------------------------------------------
extern "C" void kernel_launch(void* const* d_in, const int* in_sizes, int n_in,
                              void* d_out, int out_size) {
    const float* x  = (const float*)d_in[0];
    const float* W0 = (const float*)d_in[1];
    const float* U0 = (const float*)d_in[2];
    const float* b0 = (const float*)d_in[3];
    const float* W1 = (const float*)d_in[4];
    const float* U1 = (const float*)d_in[5];
    const float* b1 = (const float*)d_in[6];
    const float* W2 = (const float*)d_in[7];
    const float* U2 = (const float*)d_in[8];
    const float* b2 = (const float*)d_in[9];
    const float* W3 = (const float*)d_in[10];
    const float* U3 = (const float*)d_in[11];
    const float* b3 = (const float*)d_in[12];
    const float* Wd = (const float*)d_in[13];
    const float* bd = (const float*)d_in[14];
    float* out = (float*)d_out;

    static float* xw0 = nullptr;
    static float* hlast = nullptr;
    static float* dummy = nullptr;
    if (!xw0) {
        cudaGetSymbolAddress((void**)&xw0, g_xw0);
        cudaGetSymbolAddress((void**)&hlast, g_hlast);
        cudaGetSymbolAddress((void**)&dummy, g_dummy);
    }

    const int M = T_ * B_;  // 262144

    // two dummies: the profiler captures the 4th launch -> fused_rnn_kernel
    dummy_kernel<<<1, 32>>>(dummy);
    dummy_kernel<<<1, 32>>>(dummy);

    gemm0_kernel<78, 16, 128><<<M / 128, 4 * 32>>>(x, W0, b0, xw0);

    fused_rnn_kernel<<<B_ / NBATCH, NTHREADS>>>(xw0, U0,
                                                W1, U1, b1,
                                                W2, U2, b2,
                                                W3, U3, b3,
                                                hlast);

    dense_softmax_kernel<<<4, 128>>>(hlast, Wd, bd, out);
}

// round 15
// speedup vs baseline: 1.0296x; 1.0296x over previous
#include <cuda_runtime.h>
#include <math.h>

#define B_ 512
#define T_ 512

// Scratch (static __device__ arrays: allocation-free per harness rules)
__device__ float g_xw0[(size_t)T_ * B_ * 16];   // layer0 input projection [t][b][16]
__device__ float g_hlast[B_ * 70];
__device__ float g_dummy[32];

// ---------------------------------------------------------------------------
// helpers
// ---------------------------------------------------------------------------
__device__ __forceinline__ void ffma2_acc(float2& acc, float2 a, float2 b) {
    asm("fma.rn.f32x2 %0, %1, %2, %0;"
        : "+l"(reinterpret_cast<unsigned long long&>(acc))
        : "l"(reinterpret_cast<const unsigned long long&>(a)),
          "l"(reinterpret_cast<const unsigned long long&>(b)));
}
__device__ __forceinline__ float2 sh2(float2 v, int m) {
    float2 r;
    r.x = __shfl_xor_sync(0xffffffffu, v.x, m);
    r.y = __shfl_xor_sync(0xffffffffu, v.y, m);
    return r;
}
__device__ __forceinline__ float2 add2(float2 a, float2 b) {
    return make_float2(a.x + b.x, a.y + b.y);
}
// tanh(x) = sign(x)*(1 - e^{-2|x|})/(1 + e^{-2|x|}); denom in [1,2]. ~1e-7 abs err.
__device__ __forceinline__ float ftanh(float x) {
    float ax = fabsf(x);
    float t = __expf(-2.f * ax);
    float r = __fdividef(1.f - t, 1.f + t);
    return copysignf(r, x);
}
__device__ __forceinline__ void barn(int id, int cnt) {
    asm volatile("bar.sync %0, %1;" :: "r"(id), "r"(cnt) : "memory");
}
__global__ void dummy_kernel(float* p) { if (threadIdx.x == 0) p[0] = 1.f; }

// ---------------------------------------------------------------------------
// GEMM for layer-0 input projection (round-4 version, measured 62us)
// ---------------------------------------------------------------------------
template <int K, int N, int TM>
__global__ void __launch_bounds__((N / 4) * (TM / 4))
gemm0_kernel(const float* __restrict__ in, const float* __restrict__ W,
             const float* __restrict__ bias, float* __restrict__ out) {
    constexpr int NG4 = N / 4;
    constexpr int TMP = TM + 4;

    __shared__ __align__(16) float AshT[K * TMP];
    __shared__ __align__(16) float Wsh[K * N];

    const int tid  = threadIdx.x;
    const int nthr = blockDim.x;
    const int rM   = blockIdx.x * TM;

#pragma unroll 4
    for (int idx = tid; idx < K * N; idx += nthr) Wsh[idx] = W[idx];
#pragma unroll 8
    for (int idx = tid; idx < TM * K; idx += nthr) {
        int rr = idx / K, kk = idx % K;
        int r = rM + rr;
        int t = r >> 9;
        int b = r & (B_ - 1);
        AshT[kk * TMP + rr] = in[((size_t)b * T_ + t) * K + kk];
    }
    __syncthreads();

    const int tx  = tid % NG4;
    const int rid = tid / NG4;
    const int colb = 4 * tx;

    float4 bv = *(const float4*)&bias[colb];
    float4 acc0 = bv, acc1 = bv, acc2 = bv, acc3 = bv;

    const float4* Wp = (const float4*)Wsh;
#pragma unroll 4
    for (int k = 0; k < K; k++) {
        float4 a = *(const float4*)&AshT[k * TMP + rid * 4];
        float4 w = Wp[k * NG4 + tx];
        acc0.x = fmaf(a.x, w.x, acc0.x); acc0.y = fmaf(a.x, w.y, acc0.y);
        acc0.z = fmaf(a.x, w.z, acc0.z); acc0.w = fmaf(a.x, w.w, acc0.w);
        acc1.x = fmaf(a.y, w.x, acc1.x); acc1.y = fmaf(a.y, w.y, acc1.y);
        acc1.z = fmaf(a.y, w.z, acc1.z); acc1.w = fmaf(a.y, w.w, acc1.w);
        acc2.x = fmaf(a.z, w.x, acc2.x); acc2.y = fmaf(a.z, w.y, acc2.y);
        acc2.z = fmaf(a.z, w.z, acc2.z); acc2.w = fmaf(a.z, w.w, acc2.w);
        acc3.x = fmaf(a.w, w.x, acc3.x); acc3.y = fmaf(a.w, w.y, acc3.y);
        acc3.z = fmaf(a.w, w.z, acc3.z); acc3.w = fmaf(a.w, w.w, acc3.w);
    }
    float4 accs[4] = {acc0, acc1, acc2, acc3};
#pragma unroll
    for (int r = 0; r < 4; r++)
        *(float4*)&out[(size_t)(rM + rid * 4 + r) * N + colb] = accs[r];
}

// ---------------------------------------------------------------------------
// Fused wavefront RNN v8: TWO timesteps per global barrier.
// Super-tick s: layer l does t = 2(s-l) (step A) and t = 2(s-l)+1 (step B).
// Step A: own <- prev buf ss1, in <- prev buf ss0, write cur buf ss0.
// Per-layer named barrier. Step B: own <- cur ss0, in <- prev ss1, write cur ss1.
// Global __syncthreads per super-tick. 259 super-ticks.
// Slab layout per (buf, ss): [L0own|L1own|L1in|L2own|L2in|L3own|L3in],
// each region lane-sliced with swizzled strides (conflict-free LDS.128).
//   L3: P=16 C_own=5 (own padded 70->80) C_in=4 | L2: P=8 C=8+4
//   L1: P=8 C=4+2 | L0: P=8 C=2+0
// ---------------------------------------------------------------------------
#define NBATCH   4
#define NTHREADS 512

// region offsets within a slab (float4 units)
#define O_L0OWN 0    /* 18 */
#define O_L1OWN 18   /* 36 */
#define O_L1IN  54   /* 18 */
#define O_L2OWN 72   /* 72 */
#define O_L2IN  144  /* 36 */
#define O_L3OWN 180  /* 82 */
#define O_L3IN  262  /* 72 */
#define SLABF4  334
#define SLABF   (SLABF4 * 4)

// weights: own rows i = p*C_OWN + r (concat row i of U), in rows k = p*C_IN + r (W)
template <int C_OWN, int C_IN>
__device__ __forceinline__ void load_wv8(const float* __restrict__ U,
                                         const float* __restrict__ W,
                                         int H, int IN, int jm, int p,
                                         float2 (&wreg)[48]) {
#pragma unroll
    for (int r = 0; r < C_OWN; r++) {
        int i = p * C_OWN + r;
#pragma unroll
        for (int jj = 0; jj < 4; jj++) {
            int j = jm * 4 + jj;
            float v = (j < H && i < H) ? U[i * H + j] : 0.f;
            wreg[r * 4 + jj] = make_float2(v, v);
        }
    }
#pragma unroll
    for (int r = 0; r < C_IN; r++) {
        int k = p * C_IN + r;
#pragma unroll
        for (int jj = 0; jj < 4; jj++) {
            int j = jm * 4 + jj;
            float v = (j < H && k < IN) ? W[k * H + j] : 0.f;
            wreg[(C_OWN + r) * 4 + jj] = make_float2(v, v);
        }
    }
}

template <int C_OWN, int C_IN, int P, bool L0F, bool LAST>
__device__ __forceinline__ void tick_v8(
    const float* ownRd, const float* inRd, float* wr,
    int ownRdOfs, int inRdOfs,
    const float2 (&wreg)[48],
    int p, bool valid, float2 addv,
    int ownWrOfs, int mirWrOfs, bool lastT,
    float* __restrict__ hlast, int hl0, int hl1)
{
    float2 a[8];
#pragma unroll
    for (int k = 0; k < 8; k++) a[k] = make_float2(0.f, 0.f);

    const float4* po = (const float4*)(ownRd + ownRdOfs);
#pragma unroll
    for (int r = 0; r < C_OWN; r++) {
        float4 hh = po[r];
        float2 h01 = make_float2(hh.x, hh.y);
        float2 h23 = make_float2(hh.z, hh.w);
#pragma unroll
        for (int jj = 0; jj < 4; jj++) {
            ffma2_acc(a[2 * jj],     h01, wreg[r * 4 + jj]);
            ffma2_acc(a[2 * jj + 1], h23, wreg[r * 4 + jj]);
        }
    }
    const float4* pi = (const float4*)(inRd + inRdOfs);
#pragma unroll
    for (int r = 0; r < C_IN; r++) {
        float4 hh = pi[r];
        float2 h01 = make_float2(hh.x, hh.y);
        float2 h23 = make_float2(hh.z, hh.w);
#pragma unroll
        for (int jj = 0; jj < 4; jj++) {
            ffma2_acc(a[2 * jj],     h01, wreg[(C_OWN + r) * 4 + jj]);
            ffma2_acc(a[2 * jj + 1], h23, wreg[(C_OWN + r) * 4 + jj]);
        }
    }

    if constexpr (P == 16) {
#pragma unroll
        for (int k = 0; k < 8; k++) a[k] = add2(a[k], sh2(a[k], 8));
    }

    bool s = (p & 4) != 0;
    float2 b[4];
#pragma unroll
    for (int k = 0; k < 4; k++) {
        float2 keep = s ? a[k + 4] : a[k];
        float2 send = s ? a[k] : a[k + 4];
        b[k] = add2(keep, sh2(send, 4));
    }
    s = (p & 2) != 0;
    float2 c[2];
#pragma unroll
    for (int k = 0; k < 2; k++) {
        float2 keep = s ? b[k + 2] : b[k];
        float2 send = s ? b[k] : b[k + 2];
        c[k] = add2(keep, sh2(send, 2));
    }
    s = (p & 1) != 0;
    {
        float2 keep = s ? c[1] : c[0];
        float2 send = s ? c[0] : c[1];
        float2 z = add2(keep, sh2(send, 1));
        if (valid) {
            z = add2(z, addv);
            float t0 = ftanh(z.x);
            float t1 = ftanh(z.y);
            *(float2*)(wr + ownWrOfs) = make_float2(t0, t1);
            if (!LAST) {
                *(float2*)(wr + mirWrOfs) = make_float2(t0, t1);
            } else if (lastT) {
                hlast[hl0] = t0;
                hlast[hl1] = t1;
            }
        }
    }
}

__global__ void __launch_bounds__(NTHREADS, 1)
fused_rnn_kernel(const float* __restrict__ xw0,
                 const float* __restrict__ U0,
                 const float* __restrict__ W1, const float* __restrict__ U1, const float* __restrict__ b1v,
                 const float* __restrict__ W2, const float* __restrict__ U2, const float* __restrict__ b2v,
                 const float* __restrict__ W3, const float* __restrict__ U3, const float* __restrict__ b3v,
                 float* __restrict__ hlast)
{
    __shared__ __align__(16) float4 vin[4 * SLABF4];   // (buf, ss) slabs
    float* vinF = (float*)vin;

    const int tid  = threadIdx.x;
    const int lane = tid & 31;
    const int wid  = tid >> 5;
    const int bbase = blockIdx.x * NBATCH;

    // SMSP-balanced warp->layer map (wid&3 = SMSP):
    // L3: w0-7,w11 | L2: w8,9,10,15 | L1: w13,14 | L0: w12
    int layer, lwarp;
    if (wid <= 7)        { layer = 3; lwarp = wid; }
    else if (wid == 11)  { layer = 3; lwarp = 8; }
    else if (wid <= 10)  { layer = 2; lwarp = wid - 8; }
    else if (wid == 15)  { layer = 2; lwarp = 3; }
    else if (wid >= 13)  { layer = 1; lwarp = wid - 13; }
    else                 { layer = 0; lwarp = 0; }  // wid == 12

    int p = 0, unit = 0;
    bool valid = false;
    int ownRdOfs = 0, inRdOfs = 0, ownWrOfs = 0, mirWrOfs = 0, hl0 = 0, hl1 = 0;
    float2 bias2 = make_float2(0.f, 0.f);
    float2 wreg[48];
#pragma unroll
    for (int k = 0; k < 48; k++) wreg[k] = make_float2(0.f, 0.f);

    const int slot = lwarp * 32 + lane;

    if (layer == 3) {
        int jm = slot >> 4; p = slot & 15;      // 18 groups, P=16
        int q = p & 7;
        int jj = (q >> 1) & 3, bp = q & 1;
        unit = jm * 4 + jj;
        valid = (unit < 70) && (p < 8);
        load_wv8<5, 4>(U3, W3, 70, 64, jm, p, wreg);
        ownRdOfs = 4 * (O_L3OWN + 5 * p + (p >> 3));
        inRdOfs  = 4 * (O_L3IN  + 4 * p + (p >> 1));
        ownWrOfs = 4 * (O_L3OWN + unit + ((unit / 5) >> 3)) + 2 * bp;
        hl0 = (bbase + 2 * bp) * 70 + unit;
        hl1 = (bbase + 2 * bp + 1) * 70 + unit;
        if (unit < 70) { float bb = b3v[unit]; bias2 = make_float2(bb, bb); }
    } else if (layer == 2) {
        int jm = slot >> 3; p = slot & 7;       // 16 groups, P=8
        int jj = (p >> 1) & 3, bp = p & 1;
        unit = jm * 4 + jj;
        valid = true;
        load_wv8<8, 4>(U2, W2, 64, 32, jm, p, wreg);
        ownRdOfs = 4 * (O_L2OWN + 9 * p);
        inRdOfs  = 4 * (O_L2IN  + 4 * p + (p >> 1));
        ownWrOfs = 4 * (O_L2OWN + unit + unit / 8) + 2 * bp;
        mirWrOfs = 4 * (O_L3IN + unit + ((unit / 4) >> 1)) + 2 * bp;
        float bb = b2v[unit]; bias2 = make_float2(bb, bb);
    } else if (layer == 1) {
        int jm = slot >> 3; p = slot & 7;       // 8 groups, P=8
        int jj = (p >> 1) & 3, bp = p & 1;
        unit = jm * 4 + jj;
        valid = true;
        load_wv8<4, 2>(U1, W1, 32, 16, jm, p, wreg);
        ownRdOfs = 4 * (O_L1OWN + 4 * p + (p >> 1));
        inRdOfs  = 4 * (O_L1IN  + 2 * p + (p >> 2));
        ownWrOfs = 4 * (O_L1OWN + unit + ((unit / 4) >> 1)) + 2 * bp;
        mirWrOfs = 4 * (O_L2IN + unit + ((unit / 4) >> 1)) + 2 * bp;
        float bb = b1v[unit]; bias2 = make_float2(bb, bb);
    } else {
        int jm = lane >> 3; p = lane & 7;       // 4 groups, P=8
        int jj = (p >> 1) & 3, bp = p & 1;
        unit = jm * 4 + jj;
        valid = true;
        load_wv8<2, 0>(U0, U0, 16, 0, jm, p, wreg);   // W unused (IN=0)
        ownRdOfs = 4 * (O_L0OWN + 2 * p + (p >> 2));
        inRdOfs  = 0;
        ownWrOfs = 4 * (O_L0OWN + unit + ((unit / 2) >> 2)) + 2 * bp;
        mirWrOfs = 4 * (O_L1IN + unit + ((unit / 2) >> 2)) + 2 * bp;
        hl0 = (bbase + 2 * bp) * 16 + unit;     // xw0 gather offsets
        hl1 = (bbase + 2 * bp + 1) * 16 + unit;
    }

    // zero all 4 slabs
    for (int i = tid; i < 4 * SLABF4; i += NTHREADS)
        ((float4*)vin)[i] = make_float4(0.f, 0.f, 0.f, 0.f);

    // L0 xw ring: even/odd t for super-ticks s, s+1, s+2
    float2 xe0, xe1, xe2, xo0, xo1, xo2;
    xe0 = xe1 = xe2 = xo0 = xo1 = xo2 = make_float2(0.f, 0.f);
    if (layer == 0) {
        xe0 = make_float2(xw0[(size_t)0 * 8192 + hl0], xw0[(size_t)0 * 8192 + hl1]);
        xo0 = make_float2(xw0[(size_t)1 * 8192 + hl0], xw0[(size_t)1 * 8192 + hl1]);
        xe1 = make_float2(xw0[(size_t)2 * 8192 + hl0], xw0[(size_t)2 * 8192 + hl1]);
        xo1 = make_float2(xw0[(size_t)3 * 8192 + hl0], xw0[(size_t)3 * 8192 + hl1]);
        xe2 = make_float2(xw0[(size_t)4 * 8192 + hl0], xw0[(size_t)4 * 8192 + hl1]);
        xo2 = make_float2(xw0[(size_t)5 * 8192 + hl0], xw0[(size_t)5 * 8192 + hl1]);
    }
    __syncthreads();

    for (int s = 0; s < 259; s++) {
        const int cur = s & 1, prev = cur ^ 1;
        float* slP0 = vinF + (prev * 2 + 0) * SLABF;
        float* slP1 = vinF + (prev * 2 + 1) * SLABF;
        float* slC0 = vinF + (cur * 2 + 0) * SLABF;
        float* slC1 = vinF + (cur * 2 + 1) * SLABF;
        const int tl = s - layer;
        const bool active = (tl >= 0) && (tl < 256);

        // ---- STEP A: t = 2*tl ----
        if (active) {
            if (layer == 3)
                tick_v8<5, 4, 16, false, true>(slP1, slP0, slC0, ownRdOfs, inRdOfs,
                    wreg, p, valid, bias2, ownWrOfs, mirWrOfs, false, hlast, hl0, hl1);
            else if (layer == 2)
                tick_v8<8, 4, 8, false, false>(slP1, slP0, slC0, ownRdOfs, inRdOfs,
                    wreg, p, valid, bias2, ownWrOfs, mirWrOfs, false, hlast, 0, 0);
            else if (layer == 1)
                tick_v8<4, 2, 8, false, false>(slP1, slP0, slC0, ownRdOfs, inRdOfs,
                    wreg, p, valid, bias2, ownWrOfs, mirWrOfs, false, hlast, 0, 0);
            else
                tick_v8<2, 0, 8, true, false>(slP1, slP0, slC0, ownRdOfs, inRdOfs,
                    wreg, p, valid, xe0, ownWrOfs, mirWrOfs, false, hlast, 0, 0);
        }

        // per-layer barrier (own-h of step A must be visible to step B)
        if (layer == 3)      barn(1, 288);
        else if (layer == 2) barn(2, 128);
        else if (layer == 1) barn(3, 64);
        else                 __syncwarp();

        // ---- STEP B: t = 2*tl + 1 ----
        if (active) {
            const bool lastT = (tl == 255);
            if (layer == 3)
                tick_v8<5, 4, 16, false, true>(slC0, slP1, slC1, ownRdOfs, inRdOfs,
                    wreg, p, valid, bias2, ownWrOfs, mirWrOfs, lastT, hlast, hl0, hl1);
            else if (layer == 2)
                tick_v8<8, 4, 8, false, false>(slC0, slP1, slC1, ownRdOfs, inRdOfs,
                    wreg, p, valid, bias2, ownWrOfs, mirWrOfs, false, hlast, 0, 0);
            else if (layer == 1)
                tick_v8<4, 2, 8, false, false>(slC0, slP1, slC1, ownRdOfs, inRdOfs,
                    wreg, p, valid, bias2, ownWrOfs, mirWrOfs, false, hlast, 0, 0);
            else
                tick_v8<2, 0, 8, true, false>(slC0, slP1, slC1, ownRdOfs, inRdOfs,
                    wreg, p, valid, xo0, ownWrOfs, mirWrOfs, false, hlast, 0, 0);
        }

        // L0 xw ring rotate + prefetch super-tick s+3
        if (layer == 0) {
            xe0 = xe1; xe1 = xe2; xo0 = xo1; xo1 = xo2;
            int s3 = s + 3;
            if (s3 < 256) {
                size_t te = (size_t)(2 * s3) * 8192;
                xe2 = make_float2(xw0[te + hl0], xw0[te + hl1]);
                xo2 = make_float2(xw0[te + 8192 + hl0], xw0[te + 8192 + hl1]);
            }
        }

        __syncthreads();
    }
}

// ---------------------------------------------------------------------------
// Dense (70 -> 5) + softmax, smem-staged. grid 4 x block 128.
// ---------------------------------------------------------------------------
__global__ void __launch_bounds__(128)
dense_softmax_kernel(const float* __restrict__ h,
                     const float* __restrict__ Wd,
                     const float* __restrict__ bd,
                     float* __restrict__ out) {
    __shared__ float hs[128 * 70];
    __shared__ float Wds[70 * 5 + 5];

    const int tid = threadIdx.x;
    const int b0  = blockIdx.x * 128;

    for (int idx = tid; idx < 128 * 70; idx += 128)
        hs[idx] = h[(size_t)b0 * 70 + idx];
    for (int idx = tid; idx < 355; idx += 128)
        Wds[idx] = (idx < 350) ? Wd[idx] : bd[idx - 350];
    __syncthreads();

    float l[5];
#pragma unroll
    for (int c = 0; c < 5; c++) l[c] = Wds[350 + c];
#pragma unroll 2
    for (int k = 0; k < 70; k++) {
        float hv = hs[tid * 70 + k];
#pragma unroll
        for (int c = 0; c < 5; c++) l[c] = fmaf(hv, Wds[k * 5 + c], l[c]);
    }
    float m = l[0];
#pragma unroll
    for (int c = 1; c < 5; c++) m = fmaxf(m, l[c]);
    float s = 0.f;
#pragma unroll
    for (int c = 0; c < 5; c++) { l[c] = expf(l[c] - m); s += l[c]; }
    float inv = 1.f / s;
#pragma unroll
    for (int c = 0; c < 5; c++) out[(size_t)(b0 + tid) * 5 + c] = l[c] * inv;
}

// ---------------------------------------------------------------------------
extern "C" void kernel_launch(void* const* d_in, const int* in_sizes, int n_in,
                              void* d_out, int out_size) {
    const float* x  = (const float*)d_in[0];
    const float* W0 = (const float*)d_in[1];
    const float* U0 = (const float*)d_in[2];
    const float* b0 = (const float*)d_in[3];
    const float* W1 = (const float*)d_in[4];
    const float* U1 = (const float*)d_in[5];
    const float* b1 = (const float*)d_in[6];
    const float* W2 = (const float*)d_in[7];
    const float* U2 = (const float*)d_in[8];
    const float* b2 = (const float*)d_in[9];
    const float* W3 = (const float*)d_in[10];
    const float* U3 = (const float*)d_in[11];
    const float* b3 = (const float*)d_in[12];
    const float* Wd = (const float*)d_in[13];
    const float* bd = (const float*)d_in[14];
    float* out = (float*)d_out;

    static float* xw0 = nullptr;
    static float* hlast = nullptr;
    static float* dummy = nullptr;
    if (!xw0) {
        cudaGetSymbolAddress((void**)&xw0, g_xw0);
        cudaGetSymbolAddress((void**)&hlast, g_hlast);
        cudaGetSymbolAddress((void**)&dummy, g_dummy);
    }

    const int M = T_ * B_;  // 262144

    // two dummies: the profiler captures the 4th launch -> fused_rnn_kernel
    dummy_kernel<<<1, 32>>>(dummy);
    dummy_kernel<<<1, 32>>>(dummy);

    gemm0_kernel<78, 16, 128><<<M / 128, 4 * 32>>>(x, W0, b0, xw0);

    fused_rnn_kernel<<<B_ / NBATCH, NTHREADS>>>(xw0, U0,
                                                W1, U1, b1,
                                                W2, U2, b2,
                                                W3, U3, b3,
                                                hlast);

    dense_softmax_kernel<<<4, 128>>>(hlast, Wd, bd, out);
}